// round 1
// baseline (speedup 1.0000x reference)
#include <cuda_runtime.h>
#include <cstdint>

// ---------------------------------------------------------------------------
// EEGConvNetMiniV3: GCN(128->16)+BN+LReLU -> SAGPool(0.5) -> GCN(16->32)+BN+
// LReLU -> SAGPool(0.5) -> global_add_pool -> MLP 32->8->4->2 (LReLU each).
// N=200000 nodes, E=6400000 edges, single graph. edge_weigth unused (emask=1).
// b1/b2 cancel inside BatchNorm.
// ---------------------------------------------------------------------------

#define NMAX  200000
#define EMAX  6400000
#define K1MAX 100000

// -------- static device scratch (no allocations allowed) --------
__device__ float              g_hx1[NMAX * 16];   // x @ W1
__device__ float              g_h1 [NMAX * 16];   // agg1 -> bn/lrelu in place
__device__ float              g_p1 [NMAX];        // h1 @ Wr1
__device__ float              g_s1 [NMAX];        // score1
__device__ unsigned long long g_key1[NMAX];
__device__ int                g_inv1[NMAX];
__device__ float              g_hk [K1MAX * 16];  // pooled features (stage-2 input)
__device__ float              g_hx2[K1MAX * 32];  // hk @ W2
__device__ float              g_h2 [K1MAX * 32];  // agg2 -> bn/lrelu in place
__device__ float              g_p2 [K1MAX];
__device__ float              g_s2 [K1MAX];
__device__ unsigned long long g_key2[K1MAX];
__device__ int                g_src2[EMAX];
__device__ int                g_dst2[EMAX];
__device__ double             g_stats1[32];       // [sum(16) | sumsq(16)]
__device__ double             g_stats2[64];       // [sum(32) | sumsq(32)]
__device__ float              g_pooled[32];
__device__ int                g_n1;
__device__ int                g_e2;

struct Sel {
    unsigned long long prefix;
    unsigned int       krem;
    unsigned int       hist[256];
};
__device__ Sel g_sel[2];

// ---------------------------------------------------------------------------
__global__ void k_init(int N, int K1, int K2) {
    long long tid    = blockIdx.x * (long long)blockDim.x + threadIdx.x;
    long long stride = (long long)gridDim.x * blockDim.x;
    for (long long t = tid; t < (long long)N * 16; t += stride) g_h1[t] = 0.f;
    for (long long t = tid; t < (long long)K1 * 32; t += stride) g_h2[t] = 0.f;
    for (long long t = tid; t < N; t += stride) g_inv1[t] = -1;
    if (tid < 32)  g_stats1[tid] = 0.0;
    if (tid < 64)  g_stats2[tid] = 0.0;
    if (tid < 32)  g_pooled[tid] = 0.f;
    if (tid < 256) { g_sel[0].hist[tid] = 0u; g_sel[1].hist[tid] = 0u; }
    if (tid == 0) {
        g_n1 = 0; g_e2 = 0;
        g_sel[0].prefix = 0ull; g_sel[0].krem = (unsigned)K1;
        g_sel[1].prefix = 0ull; g_sel[1].krem = (unsigned)K2;
    }
}

// x (N x 128) @ W1 (128 x 16) -> g_hx1
__global__ __launch_bounds__(256) void k_gemm1(const float* __restrict__ x,
                                               const float* __restrict__ W1, int N) {
    __shared__ float sW[128 * 16];
    __shared__ float sX[16 * 128];
    int tid  = threadIdx.x;
    int row0 = blockIdx.x * 16;
    for (int j = tid; j < 2048; j += 256) sW[j] = W1[j];
    for (int j = tid; j < 2048; j += 256) {
        int r = j >> 7, c = j & 127;
        int row = row0 + r;
        sX[j] = (row < N) ? x[(long long)row * 128 + c] : 0.f;
    }
    __syncthreads();
    int r = tid >> 4, f = tid & 15;
    float acc = 0.f;
#pragma unroll 16
    for (int k = 0; k < 128; k++) acc += sX[r * 128 + k] * sW[k * 16 + f];
    int row = row0 + r;
    if (row < N) g_hx1[(long long)row * 16 + f] = acc;
}

// scatter-add 16-dim messages: agg[d] += hx1[s], one thread per (edge,feature)
__global__ __launch_bounds__(256) void k_edge_agg16(const int* __restrict__ src,
                                                    const int* __restrict__ dst,
                                                    long long E16) {
    long long t = blockIdx.x * (long long)blockDim.x + threadIdx.x;
    if (t >= E16) return;
    int       f = (int)(t & 15);
    long long e = t >> 4;
    int s = src[e], d = dst[e];
    atomicAdd(&g_h1[(long long)d * 16 + f], g_hx1[(long long)s * 16 + f]);
}

template <int F>
__global__ __launch_bounds__(256) void k_bnstats(int n) {
    const float* h     = (F == 16) ? g_h1 : g_h2;
    double*      stats = (F == 16) ? g_stats1 : g_stats2;
    int tid = threadIdx.x;
    int f   = tid % F;
    const int rpb = 256 / F;
    float s = 0.f, sq = 0.f;
    for (long long row = blockIdx.x * (long long)rpb + tid / F; row < n;
         row += (long long)gridDim.x * rpb) {
        float v = h[row * F + f];
        s += v; sq += v * v;
    }
    __shared__ float sh[256], shq[256];
    sh[tid] = s; shq[tid] = sq;
    __syncthreads();
    if (tid < F) {
        float a = 0.f, b = 0.f;
        for (int j = tid; j < 256; j += F) { a += sh[j]; b += shq[j]; }
        atomicAdd(&stats[f],     (double)a);
        atomicAdd(&stats[F + f], (double)b);
    }
}

// BN (training stats) + LeakyReLU in place, plus score precomputation:
//   p[i] = h[i] @ Wr   (to be edge-aggregated),  s[i] = h[i] @ Wroot + br
template <int F>
__global__ __launch_bounds__(256) void k_bnapply(int n,
                                                 const float* __restrict__ gam,
                                                 const float* __restrict__ beta,
                                                 const float* __restrict__ Wr,
                                                 const float* __restrict__ br,
                                                 const float* __restrict__ Wroot) {
    float*  h     = (F == 16) ? g_h1 : g_h2;
    float*  p     = (F == 16) ? g_p1 : g_p2;
    float*  s     = (F == 16) ? g_s1 : g_s2;
    double* stats = (F == 16) ? g_stats1 : g_stats2;

    __shared__ float smu[F], ssc[F], sbe[F], sWr[F], sWt[F];
    if (threadIdx.x < F) {
        int    f   = threadIdx.x;
        double mu  = stats[f] / (double)n;
        double var = stats[F + f] / (double)n - mu * mu;
        smu[f] = (float)mu;
        ssc[f] = gam[f] * rsqrtf((float)var + 1e-5f);
        sbe[f] = beta[f];
        sWr[f] = Wr[f];
        sWt[f] = Wroot[f];
    }
    __syncthreads();
    long long i = blockIdx.x * (long long)blockDim.x + threadIdx.x;
    if (i >= n) return;
    float dotp = 0.f, dotr = 0.f;
#pragma unroll
    for (int f = 0; f < F; f++) {
        float v = h[i * F + f];
        v = (v - smu[f]) * ssc[f] + sbe[f];
        v = v > 0.f ? v : 0.01f * v;
        h[i * F + f] = v;
        dotp += v * sWr[f];
        dotr += v * sWt[f];
    }
    p[i] = dotp;
    s[i] = dotr + br[0];
}

__global__ __launch_bounds__(256) void k_edge_scalar1(const int* __restrict__ src,
                                                      const int* __restrict__ dst,
                                                      long long E) {
    long long e = blockIdx.x * (long long)blockDim.x + threadIdx.x;
    if (e >= E) return;
    atomicAdd(&g_s1[dst[e]], g_p1[src[e]]);
}

__global__ __launch_bounds__(256) void k_makekeys(int which, int n) {
    const float*        s   = which ? g_s2 : g_s1;
    unsigned long long* key = which ? g_key2 : g_key1;
    long long i = blockIdx.x * (long long)blockDim.x + threadIdx.x;
    if (i >= n) return;
    unsigned u = __float_as_uint(s[i]);
    u = (u & 0x80000000u) ? ~u : (u | 0x80000000u);
    key[i] = ((unsigned long long)u << 32) | (unsigned long long)(0xFFFFFFFFu - (unsigned)i);
}

// MSB radix-select over unique 64-bit keys: 8 passes of (hist, scan)
__global__ __launch_bounds__(256) void k_hist(int which, int n, int pass) {
    const unsigned long long* key = which ? g_key2 : g_key1;
    __shared__ unsigned int sh[256];
    for (int j = threadIdx.x; j < 256; j += blockDim.x) sh[j] = 0u;
    __syncthreads();
    unsigned long long prefix = g_sel[which].prefix;
    int                shift  = 56 - 8 * pass;
    unsigned long long mask   = pass ? (~0ull << (64 - 8 * pass)) : 0ull;
    for (long long i = blockIdx.x * (long long)blockDim.x + threadIdx.x; i < n;
         i += (long long)gridDim.x * blockDim.x) {
        unsigned long long k = key[i];
        if (((k ^ prefix) & mask) == 0ull)
            atomicAdd(&sh[(unsigned)(k >> shift) & 255u], 1u);
    }
    __syncthreads();
    for (int j = threadIdx.x; j < 256; j += blockDim.x)
        if (sh[j]) atomicAdd(&g_sel[which].hist[j], sh[j]);
}

__global__ void k_scan(int which, int pass) {
    Sel* S = &g_sel[which];
    if (threadIdx.x == 0) {
        unsigned int       krem = S->krem;
        unsigned long long acc  = 0ull;
        int                chosen = 0;
        for (int d = 255; d >= 0; --d) {
            unsigned c = S->hist[d];
            if (acc + c >= (unsigned long long)krem) { chosen = d; break; }
            acc += c;
        }
        S->krem = krem - (unsigned)acc;
        S->prefix |= ((unsigned long long)chosen) << (56 - 8 * pass);
    }
    __syncthreads();
    for (int j = threadIdx.x; j < 256; j += blockDim.x) S->hist[j] = 0u;
}

// keep key >= threshold; hk[new] = h1[old] * tanh(s1[old]); build inv map
__global__ __launch_bounds__(256) void k_compact_nodes(int N) {
    long long i = blockIdx.x * (long long)blockDim.x + threadIdx.x;
    if (i >= N) return;
    if (g_key1[i] >= g_sel[0].prefix) {
        int   pos = atomicAdd(&g_n1, 1);
        g_inv1[i] = pos;
        float t = tanhf(g_s1[i]);
#pragma unroll
        for (int f = 0; f < 16; f++)
            g_hk[(long long)pos * 16 + f] = g_h1[i * 16 + f] * t;
    }
}

__global__ __launch_bounds__(256) void k_compact_edges(const int* __restrict__ src,
                                                       const int* __restrict__ dst,
                                                       long long E) {
    long long e = blockIdx.x * (long long)blockDim.x + threadIdx.x;
    if (e >= E) return;
    int ns = g_inv1[src[e]];
    int nd = g_inv1[dst[e]];
    if ((ns | nd) >= 0) {
        int pos = atomicAdd(&g_e2, 1);
        g_src2[pos] = ns;
        g_dst2[pos] = nd;
    }
}

// hk (K1 x 16) @ W2 (16 x 32) -> g_hx2
__global__ __launch_bounds__(256) void k_gemm2(const float* __restrict__ W2, int K1) {
    __shared__ float sW[16 * 32];
    for (int j = threadIdx.x; j < 512; j += 256) sW[j] = W2[j];
    __syncthreads();
    long long t = blockIdx.x * (long long)blockDim.x + threadIdx.x;
    if (t >= (long long)K1 * 32) return;
    int       f = (int)(t & 31);
    long long r = t >> 5;
    float acc = 0.f;
#pragma unroll
    for (int k = 0; k < 16; k++) acc += g_hk[r * 16 + k] * sW[k * 32 + f];
    g_hx2[t] = acc;
}

__global__ __launch_bounds__(256) void k_edge_agg32() {
    long long total = (long long)g_e2 * 32;
    for (long long t = blockIdx.x * (long long)blockDim.x + threadIdx.x; t < total;
         t += (long long)gridDim.x * blockDim.x) {
        int       f = (int)(t & 31);
        long long e = t >> 5;
        int s = g_src2[e], d = g_dst2[e];
        atomicAdd(&g_h2[(long long)d * 32 + f], g_hx2[(long long)s * 32 + f]);
    }
}

__global__ __launch_bounds__(256) void k_edge_scalar2() {
    long long total = (long long)g_e2;
    for (long long e = blockIdx.x * (long long)blockDim.x + threadIdx.x; e < total;
         e += (long long)gridDim.x * blockDim.x)
        atomicAdd(&g_s2[g_dst2[e]], g_p2[g_src2[e]]);
}

// sum over kept stage-2 nodes of h2 * tanh(s2) -> g_pooled[32]
__global__ __launch_bounds__(256) void k_pool(int K1) {
    __shared__ float part[32];
    if (threadIdx.x < 32) part[threadIdx.x] = 0.f;
    __syncthreads();
    unsigned long long T = g_sel[1].prefix;
    int   f   = threadIdx.x & 31;
    float acc = 0.f;
    for (long long t = blockIdx.x * (long long)blockDim.x + threadIdx.x;
         t < (long long)K1 * 32; t += (long long)gridDim.x * blockDim.x) {
        long long i = t >> 5;
        if (g_key2[i] >= T) acc += g_h2[t] * tanhf(g_s2[i]);
    }
    atomicAdd(&part[f], acc);
    __syncthreads();
    if (threadIdx.x < 32) atomicAdd(&g_pooled[threadIdx.x], part[threadIdx.x]);
}

__global__ void k_mlp(const float* __restrict__ fw1, const float* __restrict__ fb1,
                      const float* __restrict__ fw2, const float* __restrict__ fb2,
                      const float* __restrict__ fw3, const float* __restrict__ fb3,
                      float* __restrict__ out) {
    if (threadIdx.x == 0 && blockIdx.x == 0) {
        float a[8], b[4];
#pragma unroll
        for (int o = 0; o < 8; o++) {
            float v = fb1[o];
            for (int j = 0; j < 32; j++) v += g_pooled[j] * fw1[j * 8 + o];
            a[o] = v > 0.f ? v : 0.01f * v;
        }
#pragma unroll
        for (int o = 0; o < 4; o++) {
            float v = fb2[o];
            for (int j = 0; j < 8; j++) v += a[j] * fw2[j * 4 + o];
            b[o] = v > 0.f ? v : 0.01f * v;
        }
#pragma unroll
        for (int o = 0; o < 2; o++) {
            float v = fb3[o];
            for (int j = 0; j < 4; j++) v += b[j] * fw3[j * 2 + o];
            out[o] = v > 0.f ? v : 0.01f * v;
        }
    }
}

// ---------------------------------------------------------------------------
extern "C" void kernel_launch(void* const* d_in, const int* in_sizes, int n_in,
                              void* d_out, int out_size) {
    const float* x    = (const float*)d_in[0];
    const int*   ei   = (const int*)d_in[1];
    long long    E    = (long long)in_sizes[2];   // edge_weigth count
    int          N    = in_sizes[3];              // batch count
    const int*   src  = ei;
    const int*   dst  = ei + E;
    int K1 = (N + 1) / 2;
    int K2 = (K1 + 1) / 2;

    const float* W1     = (const float*)d_in[4];
    const float* g1     = (const float*)d_in[6];
    const float* be1    = (const float*)d_in[7];
    const float* Wr1    = (const float*)d_in[8];
    const float* br1    = (const float*)d_in[9];
    const float* Wroot1 = (const float*)d_in[10];
    const float* W2     = (const float*)d_in[11];
    const float* g2     = (const float*)d_in[13];
    const float* be2    = (const float*)d_in[14];
    const float* Wr2    = (const float*)d_in[15];
    const float* br2    = (const float*)d_in[16];
    const float* Wroot2 = (const float*)d_in[17];
    const float* fw1    = (const float*)d_in[18];
    const float* fb1    = (const float*)d_in[19];
    const float* fw2    = (const float*)d_in[20];
    const float* fb2    = (const float*)d_in[21];
    const float* fw3    = (const float*)d_in[22];
    const float* fb3    = (const float*)d_in[23];
    float*       out    = (float*)d_out;

    // ---- init scratch ----
    k_init<<<2048, 256>>>(N, K1, K2);

    // ---- stage 1: GCN + BN + LReLU ----
    k_gemm1<<<(N + 15) / 16, 256>>>(x, W1, N);
    {
        long long E16 = E * 16;
        k_edge_agg16<<<(int)((E16 + 255) / 256), 256>>>(src, dst, E16);
    }
    k_bnstats<16><<<512, 256>>>(N);
    k_bnapply<16><<<(N + 255) / 256, 256>>>(N, g1, be1, Wr1, br1, Wroot1);

    // ---- stage 1 score + top-k select ----
    k_edge_scalar1<<<(int)((E + 255) / 256), 256>>>(src, dst, E);
    k_makekeys<<<(N + 255) / 256, 256>>>(0, N);
    for (int p = 0; p < 8; p++) {
        k_hist<<<256, 256>>>(0, N, p);
        k_scan<<<1, 256>>>(0, p);
    }
    k_compact_nodes<<<(N + 255) / 256, 256>>>(N);
    k_compact_edges<<<(int)((E + 255) / 256), 256>>>(src, dst, E);

    // ---- stage 2: GCN + BN + LReLU ----
    k_gemm2<<<(int)(((long long)K1 * 32 + 255) / 256), 256>>>(W2, K1);
    k_edge_agg32<<<8192, 256>>>();
    k_bnstats<32><<<512, 256>>>(K1);
    k_bnapply<32><<<(K1 + 255) / 256, 256>>>(K1, g2, be2, Wr2, br2, Wroot2);

    // ---- stage 2 score + top-k select ----
    k_edge_scalar2<<<2048, 256>>>();
    k_makekeys<<<(K1 + 255) / 256, 256>>>(1, K1);
    for (int p = 0; p < 8; p++) {
        k_hist<<<256, 256>>>(1, K1, p);
        k_scan<<<1, 256>>>(1, p);
    }

    // ---- global add pool + MLP ----
    k_pool<<<512, 256>>>(K1);
    k_mlp<<<1, 32>>>(fw1, fb1, fw2, fb2, fw3, fb3, out);
}